// round 2
// baseline (speedup 1.0000x reference)
#include <cuda_runtime.h>
#include <cuda_bf16.h>
#include <cstdint>

// ======================= problem constants =======================
static constexpr int Q    = 2048;
static constexpr int S    = 8;
static constexpr int D    = 2048;
static constexpr int SP   = 100;
static constexpr int NCLS = 20;
static constexpr int MR = Q * S;    // 16384 target frames
static constexpr int NR = SP * S;   // 800 support frames

// GEMM tiling
static constexpr int BM = 128;
static constexpr int BN = 160;          // 800 = 5 * 160
static constexpr int BK = 64;           // 64 bf16 = 128B row (swizzle atom)
static constexpr int NCHUNK = D / BK;   // 32

static constexpr int STAGE_A = BM * 128;   // 16384 B
static constexpr int STAGE_B = BN * 128;   // 20480 B
static constexpr int SM_BYTES = 2 * STAGE_A + 2 * STAGE_B;  // 73728

// ======================= device scratch =======================
__device__ __nv_bfloat16 g_A[(size_t)MR * D];      // 64 MB
__device__ __nv_bfloat16 g_B[(size_t)NR * D];      // 3.2 MB
__device__ float g_normT[MR];
__device__ float g_normS[NR];
__device__ float g_dist[(size_t)MR * NR];          // 52 MB, [m][n]
__device__ float g_cum[(size_t)SP * Q];            // [sp][q]

// ======================= asm helpers (generic-target safe) =======================
__device__ __forceinline__ uint32_t smem_to_u32(const void* smem_ptr) {
    uint32_t addr;
    asm("{ .reg .u64 tmp; cvta.to.shared.u64 tmp, %1; cvt.u32.u64 %0, tmp; }"
        : "=r"(addr) : "l"(smem_ptr));
    return addr;
}

__device__ __forceinline__ void cp_async16(uint32_t dst, const void* src) {
    asm volatile("cp.async.cg.shared.global [%0], [%1], 16;" :: "r"(dst), "l"(src));
}
__device__ __forceinline__ void cp_commit() {
    asm volatile("cp.async.commit_group;");
}
template <int N>
__device__ __forceinline__ void cp_wait() {
    asm volatile("cp.async.wait_group %0;" :: "n"(N));
}

__device__ __forceinline__ void ldsm_x4(uint32_t r[4], uint32_t addr) {
    asm volatile("ldmatrix.sync.aligned.m8n8.x4.shared.b16 {%0,%1,%2,%3}, [%4];"
        : "=r"(r[0]), "=r"(r[1]), "=r"(r[2]), "=r"(r[3]) : "r"(addr));
}
__device__ __forceinline__ void ldsm_x2(uint32_t r[2], uint32_t addr) {
    asm volatile("ldmatrix.sync.aligned.m8n8.x2.shared.b16 {%0,%1}, [%2];"
        : "=r"(r[0]), "=r"(r[1]) : "r"(addr));
}
__device__ __forceinline__ void mma16816(float c[4], const uint32_t a[4], const uint32_t b[2]) {
    asm volatile(
        "mma.sync.aligned.m16n8k16.row.col.f32.bf16.bf16.f32 "
        "{%0,%1,%2,%3}, {%4,%5,%6,%7}, {%8,%9}, {%0,%1,%2,%3};"
        : "+f"(c[0]), "+f"(c[1]), "+f"(c[2]), "+f"(c[3])
        : "r"(a[0]), "r"(a[1]), "r"(a[2]), "r"(a[3]), "r"(b[0]), "r"(b[1]));
}

// ======================= kernel 1: fp32 -> bf16 + row norms =======================
__global__ void __launch_bounds__(256) convert_norm_kernel(const float* __restrict__ src, int which) {
    __nv_bfloat16* dst = which ? g_B : g_A;
    float* norms = which ? g_normS : g_normT;
    const int row = blockIdx.x;

    const float4* s = reinterpret_cast<const float4*>(src) + (size_t)row * (D / 4);
    uint2* d = reinterpret_cast<uint2*>(dst) + (size_t)row * (D / 4);

    float ss = 0.f;
    for (int i = threadIdx.x; i < D / 4; i += blockDim.x) {
        float4 v = s[i];
        ss = fmaf(v.x, v.x, fmaf(v.y, v.y, fmaf(v.z, v.z, fmaf(v.w, v.w, ss))));
        uint32_t b0 = __bfloat16_as_ushort(__float2bfloat16(v.x));
        uint32_t b1 = __bfloat16_as_ushort(__float2bfloat16(v.y));
        uint32_t b2 = __bfloat16_as_ushort(__float2bfloat16(v.z));
        uint32_t b3 = __bfloat16_as_ushort(__float2bfloat16(v.w));
        d[i] = make_uint2(b0 | (b1 << 16), b2 | (b3 << 16));
    }
    for (int o = 16; o > 0; o >>= 1) ss += __shfl_down_sync(0xFFFFFFFFu, ss, o);
    __shared__ float ws[8];
    if ((threadIdx.x & 31) == 0) ws[threadIdx.x >> 5] = ss;
    __syncthreads();
    if (threadIdx.x == 0) {
        float t = 0.f;
        #pragma unroll
        for (int w = 0; w < 8; w++) t += ws[w];
        norms[row] = sqrtf(t);
    }
}

// ======================= kernel 2: HMMA GEMM + dist epilogue =======================
// SMEM: A0 @0, A1 @STAGE_A, B0 @2*STAGE_A, B1 @2*STAGE_A+STAGE_B
// Swizzle: 16B chunk c of row r stored at r*128 + ((c ^ (r&7))*16)
__device__ __forceinline__ void load_stage(uint32_t sb, int buf, int kc, int m0, int n0, int t) {
    uint32_t a_s = sb + buf * STAGE_A;
    uint32_t b_s = sb + 2 * STAGE_A + buf * STAGE_B;
    const __nv_bfloat16* gA = g_A + (size_t)m0 * D + kc * BK;
    const __nv_bfloat16* gB = g_B + (size_t)n0 * D + kc * BK;
    #pragma unroll
    for (int i = 0; i < (BM * 8) / 256; i++) {      // 4
        int idx = i * 256 + t;
        int r = idx >> 3, c = idx & 7;
        cp_async16(a_s + r * 128 + (((uint32_t)(c ^ (r & 7))) << 4),
                   gA + (size_t)r * D + c * 8);
    }
    #pragma unroll
    for (int i = 0; i < (BN * 8) / 256; i++) {      // 5
        int idx = i * 256 + t;
        int r = idx >> 3, c = idx & 7;
        cp_async16(b_s + r * 128 + (((uint32_t)(c ^ (r & 7))) << 4),
                   gB + (size_t)r * D + c * 8);
    }
    cp_commit();
}

__global__ void __launch_bounds__(256) gemm_dist_kernel() {
    extern __shared__ char smem[];
    const uint32_t sb = smem_to_u32(smem);
    const int t = threadIdx.x;
    const int l = t & 31;
    const int wid = t >> 5;
    const int wm = wid & 1;        // 2 warps over M (64 rows each)
    const int wn = wid >> 1;       // 4 warps over N (40 cols each)
    const int n0 = blockIdx.x * BN;
    const int m0 = blockIdx.y * BM;

    float acc[4][5][4];
    #pragma unroll
    for (int mt = 0; mt < 4; mt++)
        #pragma unroll
        for (int nt = 0; nt < 5; nt++)
            #pragma unroll
            for (int k = 0; k < 4; k++) acc[mt][nt][k] = 0.f;

    load_stage(sb, 0, 0, m0, n0, t);

    // per-lane ldmatrix address components
    const int la = l & 15;
    const int sa = l & 7;                 // swizzle XOR (row & 7)
    const int a_hi = l >> 4;              // 0/1: which 16B half of k16
    const int b_hi = (l >> 3) & 1;
    const uint32_t a_row_off = (uint32_t)(wm * 64 + la) * 128;
    const uint32_t b_row_off = (uint32_t)(wn * 40 + (l & 7)) * 128;   // 40,8 are mult of 8 -> row&7 == l&7

    int buf = 0;
    for (int c = 0; c < NCHUNK; c++) {
        if (c + 1 < NCHUNK) {
            load_stage(sb, buf ^ 1, c + 1, m0, n0, t);
            cp_wait<1>();
        } else {
            cp_wait<0>();
        }
        __syncthreads();

        const uint32_t a_s = sb + buf * STAGE_A;
        const uint32_t b_s = sb + 2 * STAGE_A + buf * STAGE_B;

        #pragma unroll
        for (int ks = 0; ks < BK / 16; ks++) {   // 4
            uint32_t afr[4][4], bfr[5][2];
            #pragma unroll
            for (int mt = 0; mt < 4; mt++)
                ldsm_x4(afr[mt], a_s + a_row_off + (uint32_t)(mt * 16 * 128)
                                 + (((uint32_t)((ks * 2 + a_hi) ^ sa)) << 4));
            #pragma unroll
            for (int nt = 0; nt < 5; nt++)
                ldsm_x2(bfr[nt], b_s + b_row_off + (uint32_t)(nt * 8 * 128)
                                 + (((uint32_t)((ks * 2 + b_hi) ^ sa)) << 4));
            #pragma unroll
            for (int mt = 0; mt < 4; mt++)
                #pragma unroll
                for (int nt = 0; nt < 5; nt++)
                    mma16816(acc[mt][nt], afr[mt], bfr[nt]);
        }
        __syncthreads();
        buf ^= 1;
    }

    // epilogue: dist = 1 - dot / (|t||s| + eps), store float2 (fully-covered 32B sectors)
    const int grp = l >> 2;
    const int tid4 = l & 3;
    #pragma unroll
    for (int mt = 0; mt < 4; mt++) {
        const int gm0 = m0 + wm * 64 + mt * 16 + grp;
        const float nT0 = g_normT[gm0];
        const float nT1 = g_normT[gm0 + 8];
        #pragma unroll
        for (int nt = 0; nt < 5; nt++) {
            const int gn = n0 + wn * 40 + nt * 8 + tid4 * 2;
            const float nS0 = g_normS[gn];
            const float nS1 = g_normS[gn + 1];
            float2 v0, v1;
            v0.x = 1.f - acc[mt][nt][0] / (nT0 * nS0 + 0.01f);
            v0.y = 1.f - acc[mt][nt][1] / (nT0 * nS1 + 0.01f);
            v1.x = 1.f - acc[mt][nt][2] / (nT1 * nS0 + 0.01f);
            v1.y = 1.f - acc[mt][nt][3] / (nT1 * nS1 + 0.01f);
            *reinterpret_cast<float2*>(&g_dist[(size_t)gm0 * NR + gn]) = v0;
            *reinterpret_cast<float2*>(&g_dist[(size_t)(gm0 + 8) * NR + gn]) = v1;
        }
    }
}

// ======================= kernel 3: OTAM dynamic program =======================
__device__ __forceinline__ float softmin2(float a, float b) {
    float m = fminf(a, b);
    float x = fabsf(a - b);
    return m - 0.1f * __logf(1.0f + __expf(-x * 10.0f));
}
__device__ __forceinline__ float softmin3(float a, float b, float c) {
    float m = fminf(fminf(a, b), c);
    float s = __expf((m - a) * 10.0f) + __expf((m - b) * 10.0f) + __expf((m - c) * 10.0f);
    return m - 0.1f * __logf(s);
}

template <bool TR>
__device__ __forceinline__ float otam_dp(const float d[8][8]) {
    float prev[10], cur[10];
    prev[0] = 0.f;
    float run = 0.f;
    #pragma unroll
    for (int s = 0; s < 8; s++) {
        run += TR ? d[s][0] : d[0][s];
        prev[s + 1] = run;
    }
    prev[9] = run;
    #pragma unroll
    for (int ll = 1; ll < 8; ll++) {
        cur[0] = 0.f;
        {
            float dv = TR ? d[0][ll] : d[ll][0];
            cur[1] = dv + softmin3(prev[0], prev[1], cur[0]);
        }
        #pragma unroll
        for (int m = 2; m <= 8; m++) {
            float dv = TR ? d[m - 1][ll] : d[ll][m - 1];
            cur[m] = dv + softmin2(prev[m - 1], cur[m - 1]);
        }
        cur[9] = softmin3(prev[8], prev[9], cur[8]);
        #pragma unroll
        for (int m = 0; m < 10; m++) prev[m] = cur[m];
    }
    return prev[9];
}

__global__ void __launch_bounds__(256) dp_kernel() {
    const int idx = blockIdx.x * 256 + threadIdx.x;   // 204800 pairs
    const int q = idx & (Q - 1);
    const int sp = idx >> 11;
    float d[8][8];   // d[ts][ss]
    #pragma unroll
    for (int ts = 0; ts < 8; ts++) {
        const float4* p = reinterpret_cast<const float4*>(
            g_dist + (size_t)(q * 8 + ts) * NR + sp * 8);
        float4 a = p[0], b = p[1];
        d[ts][0] = a.x; d[ts][1] = a.y; d[ts][2] = a.z; d[ts][3] = a.w;
        d[ts][4] = b.x; d[ts][5] = b.y; d[ts][6] = b.z; d[ts][7] = b.w;
    }
    g_cum[(size_t)sp * Q + q] = otam_dp<false>(d) + otam_dp<true>(d);
}

// ======================= kernel 4: per-class mean + negate =======================
__global__ void __launch_bounds__(32) class_reduce_kernel(const int* __restrict__ labels,
                                                          float* __restrict__ out) {
    const int q = blockIdx.x;
    const int c = threadIdx.x;
    if (c >= NCLS) return;
    float s = 0.f;
    int n = 0;
    for (int sp = 0; sp < SP; sp++) {
        if (labels[sp] == c) { s += g_cum[(size_t)sp * Q + q]; n++; }
    }
    out[q * NCLS + c] = -s / (float)n;
}

// ======================= launch =======================
extern "C" void kernel_launch(void* const* d_in, const int* in_sizes, int n_in,
                              void* d_out, int out_size) {
    const float* tf = (const float*)d_in[0];      // [2048, 8, 2048]
    const float* sf = (const float*)d_in[1];      // [100, 8, 2048]
    const int* labels = (const int*)d_in[2];      // [100]
    float* out = (float*)d_out;                   // [1, 2048, 20]
    (void)in_sizes; (void)n_in; (void)out_size;

    cudaFuncSetAttribute(gemm_dist_kernel,
                         cudaFuncAttributeMaxDynamicSharedMemorySize, SM_BYTES);

    convert_norm_kernel<<<MR, 256>>>(tf, 0);
    convert_norm_kernel<<<NR, 256>>>(sf, 1);
    gemm_dist_kernel<<<dim3(NR / BN, MR / BM), 256, SM_BYTES>>>();
    dp_kernel<<<(Q * SP) / 256, 256>>>();
    class_reduce_kernel<<<Q, 32>>>(labels, out);
}